// round 1
// baseline (speedup 1.0000x reference)
#include <cuda_runtime.h>

#define H 512
#define W 512

// Scratch: packed forward distances (fg<<16 | bg), one plane per image.
__device__ unsigned g_scr[2 * H * W];
// Per-column partials: phase p = img*2 + (0=fg/thickness, 1=bg/separation)
__device__ float    g_psum[4][W];
__device__ unsigned g_pcnt[4][W];

// ---------------------------------------------------------------------------
// Kernel 1: per-column forward + backward 1-D distance scans, LUT d-lookup,
// masked accumulation. One thread owns one (image, column).
// ---------------------------------------------------------------------------
__global__ __launch_bounds__(128) void morph_scan(const float* __restrict__ img,
                                                  const float* __restrict__ mask,
                                                  const float* __restrict__ tgt) {
    __shared__ float lut[1025];
    for (int v = threadIdx.x; v < 1025; v += 128) {
        lut[v] = (v == 1024) ? 1024.0f
                             : __fsqrt_rn((float)(v * v + (v & 1)) * 0.5f);
    }
    __syncthreads();

    int t   = blockIdx.x * 128 + threadIdx.x;   // 0..1023
    int im  = t >> 9;                           // 0 = img, 1 = target
    int col = t & (W - 1);

    const float* __restrict__ src = im ? tgt : img;
    unsigned* scr = g_scr + im * (H * W) + col;
    const float* ps = src + col;
    const float* pm = mask + col;

    // ---- forward scan (top -> bottom), carry starts at INF = 1024 ----
    int dfg = 1024, dbg = 1024;
#pragma unroll 8
    for (int i = 0; i < H; i++) {
        float x = ps[i * W];
        bool  b = x > 0.22f;
        dfg = b ? dfg + 1 : 0;
        dbg = b ? 0 : dbg + 1;
        unsigned f = (unsigned)min(dfg, 1024);
        unsigned g = (unsigned)min(dbg, 1024);
        scr[i * W] = (f << 16) | g;
    }

    // ---- backward scan (bottom -> top) + combine + accumulate ----
    dfg = 1024; dbg = 1024;
    float    sfg = 0.0f, sbg = 0.0f;
    unsigned cfg = 0, cbg = 0;
#pragma unroll 8
    for (int i = H - 1; i >= 0; i--) {
        unsigned pk  = scr[i * W];
        int      ffg = (int)(pk >> 16);
        int      fbg = (int)(pk & 0xFFFFu);
        bool     b   = (ffg != 0);              // fg pixel <=> fwd fg-dist > 0
        dfg = b ? dfg + 1 : 0;
        dbg = b ? 0 : dbg + 1;
        int vfg = min(ffg, min(dfg, 1024));
        int vbg = min(fbg, min(dbg, 1024));
        bool m  = pm[i * W] > 0.5f;
        int  idx = b ? vfg : vbg;               // only the owning phase matters
        float d  = lut[idx];
        bool self = m && b;
        bool selb = m && !b;
        sfg += self ? d : 0.0f;
        sbg += selb ? d : 0.0f;
        cfg += self ? 1u : 0u;
        cbg += selb ? 1u : 0u;
    }

    g_psum[im * 2 + 0][col] = sfg;
    g_psum[im * 2 + 1][col] = sbg;
    g_pcnt[im * 2 + 0][col] = cfg;
    g_pcnt[im * 2 + 1][col] = cbg;
}

// ---------------------------------------------------------------------------
// Kernel 2: deterministic tree reduction of the 512 column partials per phase
// (double precision), then the scalar loss.
// ---------------------------------------------------------------------------
__global__ __launch_bounds__(256) void morph_final(float* __restrict__ out) {
    __shared__ double   ss[4][256];
    __shared__ unsigned sc[4][256];
    int tid = threadIdx.x;

    double   s[4] = {0.0, 0.0, 0.0, 0.0};
    unsigned c[4] = {0u, 0u, 0u, 0u};
    for (int col = tid; col < W; col += 256) {
#pragma unroll
        for (int p = 0; p < 4; p++) {
            s[p] += (double)g_psum[p][col];
            c[p] += g_pcnt[p][col];
        }
    }
#pragma unroll
    for (int p = 0; p < 4; p++) { ss[p][tid] = s[p]; sc[p][tid] = c[p]; }
    __syncthreads();

    for (int off = 128; off > 0; off >>= 1) {
        if (tid < off) {
#pragma unroll
            for (int p = 0; p < 4; p++) {
                ss[p][tid] += ss[p][tid + off];
                sc[p][tid] += sc[p][tid + off];
            }
        }
        __syncthreads();
    }

    if (tid == 0) {
        const double VX2   = 21.0;        // 2 * VOXEL_SIZE
        const double TH_MU = 48.7578, TH_SD = 5.2874;
        const double SP_MU = 156.729, SP_SD = 46.1809;
        double n0 = sc[0][0] ? (double)sc[0][0] : 1.0;
        double n1 = sc[1][0] ? (double)sc[1][0] : 1.0;
        double n2 = sc[2][0] ? (double)sc[2][0] : 1.0;
        double n3 = sc[3][0] ? (double)sc[3][0] : 1.0;
        double tl = VX2 * ss[0][0] / n0;  // thickness (img fg)
        double sl = VX2 * ss[1][0] / n1;  // separation (img bg)
        double th = VX2 * ss[2][0] / n2;  // thickness (tgt fg)
        double sh = VX2 * ss[3][0] / n3;  // separation (tgt bg)
        double l1 = (tl - TH_MU) / TH_SD - (th - TH_MU) / TH_SD;
        double l7 = (sl - SP_MU) / SP_SD - (sh - SP_MU) / SP_SD;
        out[0] = (float)(0.5 * (l1 * l1 + l7 * l7));
    }
}

extern "C" void kernel_launch(void* const* d_in, const int* in_sizes, int n_in,
                              void* d_out, int out_size) {
    const float* img  = (const float*)d_in[0];
    const float* mask = (const float*)d_in[1];
    const float* tgt  = (const float*)d_in[2];
    morph_scan<<<8, 128>>>(img, mask, tgt);
    morph_final<<<1, 256>>>((float*)d_out);
}

// round 2
// speedup vs baseline: 2.9291x; 2.9291x over previous
#include <cuda_runtime.h>

#define W    512
#define H    512
#define CH   64          // rows per chunk
#define NCH  8           // chunks per column
#define CPB  16          // columns per block
#define TPB  128         // CPB * NCH
#define NBLK 64          // 2 images * (512/16)

__device__ double   g_sum[NBLK][2];   // [block][0=fg/thickness, 1=bg/separation]
__device__ unsigned g_cnt[NBLK][2];
__device__ unsigned g_ctr;            // last-block-arrival counter (reset by last block)

__global__ __launch_bounds__(TPB) void morph_all(const float* __restrict__ img,
                                                 const float* __restrict__ mask,
                                                 const float* __restrict__ tgt,
                                                 float* __restrict__ out) {
    __shared__ unsigned short fwdbuf[CH * TPB];   // [j][tid]: phase<<15 | dist
    __shared__ float    lut[1025];
    __shared__ unsigned Lpack[TPB];               // fwd dists at chunk's last row
    __shared__ unsigned Mpack[TPB];               // local bwd dists at chunk's row 0
    __shared__ double   sredA[TPB], sredB[TPB];
    __shared__ unsigned credA[TPB], credB[TPB];

    const int tid = threadIdx.x;
    for (int v = tid; v < 1025; v += TPB)
        lut[v] = (v == 1024) ? 1024.0f
                             : __fsqrt_rn((float)(v * v + (v & 1)) * 0.5f);

    const int b     = blockIdx.x;
    const int im    = b >> 5;                       // 0 = img, 1 = target
    const int cloc  = tid & (CPB - 1);
    const int chunk = tid >> 4;
    const int col   = ((b & 31) << 4) + cloc;
    const int rowBase = chunk * CH;

    const float* __restrict__ src = im ? tgt : img;
    const float* ps = src  + (size_t)rowBase * W + col;
    const float* pm = mask + (size_t)rowBase * W + col;

    // ---- phase 1: local forward scan (INF init), pack to smem ----
    int dfg = 1024, dbg = 1024, p = CH;
    bool ph0 = false;
#pragma unroll 16
    for (int j = 0; j < CH; j++) {
        float x = ps[j * W];
        bool  bb = x > 0.22f;
        if (j == 0) ph0 = bb;
        else if (p == CH && bb != ph0) p = j;       // prefix-run length
        dfg = bb ? min(dfg + 1, 1024) : 0;
        dbg = bb ? 0 : min(dbg + 1, 1024);
        fwdbuf[j * TPB + tid] =
            (unsigned short)((bb ? 0x8000u : 0u) | (unsigned)(bb ? dfg : dbg));
    }
    // analytic local-backward dist at row 0 of this chunk
    int Mfg = ph0  ? ((p < CH) ? p : 1024) : 0;
    int Mbg = !ph0 ? ((p < CH) ? p : 1024) : 0;
    Lpack[tid] = ((unsigned)dfg << 16) | (unsigned)dbg;
    Mpack[tid] = ((unsigned)Mfg << 16) | (unsigned)Mbg;
    __syncthreads();

    // ---- carries across chunks of this column ----
    int cfg = 1024, cbg = 1024;                     // fwd carry-in
    for (int m = chunk - 1; m >= 0; m--) {
        unsigned Lp = Lpack[m * CPB + cloc];
        int off = CH * (chunk - 1 - m);
        cfg = min(cfg, (int)(Lp >> 16) + off);
        cbg = min(cbg, (int)(Lp & 0xFFFFu) + off);
    }
    cfg = min(cfg, 1024); cbg = min(cbg, 1024);
    int ufg = 1024, ubg = 1024;                     // exact bwd dist at row rowBase+CH
    for (int m = chunk + 1; m < NCH; m++) {
        unsigned Mp = Mpack[m * CPB + cloc];
        int off = CH * (m - chunk - 1);
        ufg = min(ufg, (int)(Mp >> 16) + off);
        ubg = min(ubg, (int)(Mp & 0xFFFFu) + off);
    }
    ufg = min(ufg, 1024); ubg = min(ubg, 1024);

    // ---- phase 2: backward scan (exact carry init) + combine + accumulate ----
    float    sfg = 0.0f, sbg = 0.0f;
    unsigned nfg = 0u,   nbg = 0u;
#pragma unroll 16
    for (int j = CH - 1; j >= 0; j--) {
        unsigned v  = fwdbuf[j * TPB + tid];
        bool     bb = (v & 0x8000u) != 0;
        int      lf = (int)(v & 0x7FFu);
        ufg = bb ? min(ufg + 1, 1024) : 0;
        ubg = bb ? 0 : min(ubg + 1, 1024);
        int ef  = min(lf, (bb ? cfg : cbg) + j + 1);
        int eb  = bb ? ufg : ubg;
        int idx = min(ef, eb);
        float d = lut[idx];
        bool  mm = pm[j * W] > 0.5f;
        if (mm &&  bb) { sfg += d; nfg++; }
        if (mm && !bb) { sbg += d; nbg++; }
    }

    // ---- block reduction (deterministic tree, double) ----
    sredA[tid] = (double)sfg;  sredB[tid] = (double)sbg;
    credA[tid] = nfg;          credB[tid] = nbg;
    __syncthreads();
    for (int off = TPB / 2; off > 0; off >>= 1) {
        if (tid < off) {
            sredA[tid] += sredA[tid + off];
            sredB[tid] += sredB[tid + off];
            credA[tid] += credA[tid + off];
            credB[tid] += credB[tid + off];
        }
        __syncthreads();
    }

    if (tid == 0) {
        g_sum[b][0] = sredA[0];  g_sum[b][1] = sredB[0];
        g_cnt[b][0] = credA[0];  g_cnt[b][1] = credB[0];
        __threadfence();
        unsigned old = atomicAdd(&g_ctr, 1u);
        if (old == NBLK - 1) {
            // last block: deterministic-order final reduction + loss
            double   s[4] = {0.0, 0.0, 0.0, 0.0};
            unsigned c[4] = {0u, 0u, 0u, 0u};
            for (int k = 0; k < NBLK; k++) {
                int base = (k >> 5) * 2;
                s[base + 0] += g_sum[k][0];  s[base + 1] += g_sum[k][1];
                c[base + 0] += g_cnt[k][0];  c[base + 1] += g_cnt[k][1];
            }
            const double VX2   = 21.0;
            const double TH_MU = 48.7578, TH_SD = 5.2874;
            const double SP_MU = 156.729, SP_SD = 46.1809;
            double n0 = c[0] ? (double)c[0] : 1.0;
            double n1 = c[1] ? (double)c[1] : 1.0;
            double n2 = c[2] ? (double)c[2] : 1.0;
            double n3 = c[3] ? (double)c[3] : 1.0;
            double tl = VX2 * s[0] / n0;   // thickness  (img)
            double sl = VX2 * s[1] / n1;   // separation (img)
            double th = VX2 * s[2] / n2;   // thickness  (tgt)
            double sh = VX2 * s[3] / n3;   // separation (tgt)
            double l1 = (tl - TH_MU) / TH_SD - (th - TH_MU) / TH_SD;
            double l7 = (sl - SP_MU) / SP_SD - (sh - SP_MU) / SP_SD;
            out[0] = (float)(0.5 * (l1 * l1 + l7 * l7));
            g_ctr = 0;                     // reset for next graph replay
        }
    }
}

extern "C" void kernel_launch(void* const* d_in, const int* in_sizes, int n_in,
                              void* d_out, int out_size) {
    const float* img  = (const float*)d_in[0];
    const float* mask = (const float*)d_in[1];
    const float* tgt  = (const float*)d_in[2];
    morph_all<<<NBLK, TPB>>>(img, mask, tgt, (float*)d_out);
}

// round 3
// speedup vs baseline: 4.3459x; 1.4837x over previous
#include <cuda_runtime.h>

#define W    512
#define H    512
#define CH   16           // rows per chunk
#define NCH  32           // chunks per column
#define CPB  8            // columns per block
#define TPB  256          // CPB * NCH
#define NBLK 128          // 2 images * (512 / CPB)

__device__ double   g_sum[NBLK][2];   // [block][0=fg/thickness, 1=bg/separation]
__device__ unsigned g_cnt[NBLK][2];
__device__ unsigned g_ctr;

__global__ __launch_bounds__(TPB) void morph_all(const float* __restrict__ img,
                                                 const float* __restrict__ mask,
                                                 const float* __restrict__ tgt,
                                                 float* __restrict__ out) {
    __shared__ float    lut[1025];
    __shared__ unsigned Lpack[TPB];        // fwd dists at chunk's last row
    __shared__ unsigned Mpack[TPB];        // local bwd dists at chunk's row 0
    __shared__ double   wsum[8][2];        // per-warp partials
    __shared__ unsigned wcnt[8][2];
    __shared__ int      isLast;
    __shared__ double   fsum[4];
    __shared__ unsigned fcnt[4];

    const int tid = threadIdx.x;
    for (int v = tid; v < 1025; v += TPB)
        lut[v] = (v == 1024) ? 1024.0f
                             : __fsqrt_rn((float)(v * v + (v & 1)) * 0.5f);

    const int b     = blockIdx.x;
    const int im    = b >> 6;                  // 0 = img, 1 = target
    const int cloc  = tid & (CPB - 1);
    const int chunk = tid >> 3;
    const int col   = ((b & 63) << 3) + cloc;
    const int rowBase = chunk * CH;

    const float* ps = (im ? tgt : img) + (size_t)rowBase * W + col;
    const float* pm = mask              + (size_t)rowBase * W + col;

    // ---- phase 1: local forward scan, all state in registers ----
    int      lf[CH];
    unsigned bbits = 0u, mbits = 0u;
    int dfg = 1024, dbg = 1024, p = CH;
    bool ph0 = false;
#pragma unroll
    for (int j = 0; j < CH; j++) {
        bool bb = ps[j * W] > 0.22f;
        bool mm = pm[j * W] > 0.5f;
        bbits |= bb ? (1u << j) : 0u;
        mbits |= mm ? (1u << j) : 0u;
        if (j == 0) ph0 = bb;
        else if (p == CH && bb != ph0) p = j;  // prefix-run length
        dfg = bb ? dfg + 1 : 0;
        dbg = bb ? 0 : dbg + 1;
        lf[j] = bb ? dfg : dbg;                // <= 1040, fits u16
    }
    int Mfg = ph0 ? ((p < CH) ? p : 1024) : 0; // analytic local-bwd at row 0
    int Mbg = ph0 ? 0 : ((p < CH) ? p : 1024);
    Lpack[tid] = ((unsigned)dfg << 16) | (unsigned)dbg;
    Mpack[tid] = ((unsigned)Mfg << 16) | (unsigned)Mbg;
    __syncthreads();

    // ---- carries across chunks of this column ----
    int cfg = 1024, cbg = 1024;                // fwd carry-in at chunk start
    for (int m = chunk - 1; m >= 0; m--) {
        unsigned Lp  = Lpack[m * CPB + cloc];
        int      off = CH * (chunk - 1 - m);
        cfg = min(cfg, (int)(Lp >> 16) + off);
        cbg = min(cbg, (int)(Lp & 0xFFFFu) + off);
    }
    int ufg = 1024, ubg = 1024;                // exact bwd dist at row rowBase+CH
    for (int m = chunk + 1; m < NCH; m++) {
        unsigned Mp  = Mpack[m * CPB + cloc];
        int      off = CH * (m - chunk - 1);
        ufg = min(ufg, (int)(Mp >> 16) + off);
        ubg = min(ubg, (int)(Mp & 0xFFFFu) + off);
    }

    // ---- phase 2: backward scan + combine + accumulate (registers only) ----
    float    sfg = 0.0f, sbg = 0.0f;
    unsigned nfg = 0u,   nbg = 0u;
#pragma unroll
    for (int j = CH - 1; j >= 0; j--) {
        bool bb = (bbits >> j) & 1u;
        ufg = bb ? ufg + 1 : 0;
        ubg = bb ? 0 : ubg + 1;
        int ef  = min(lf[j], (bb ? cfg : cbg) + j + 1);
        int eb  = bb ? ufg : ubg;
        int idx = min(min(ef, eb), 1024);
        float d = lut[idx];
        bool mm = (mbits >> j) & 1u;
        if (mm &&  bb) { sfg += d; nfg++; }
        if (mm && !bb) { sbg += d; nbg++; }
    }

    // ---- warp shfl reduction, then cross-warp ----
#pragma unroll
    for (int o = 16; o > 0; o >>= 1) {
        sfg += __shfl_down_sync(0xFFFFFFFFu, sfg, o);
        sbg += __shfl_down_sync(0xFFFFFFFFu, sbg, o);
        nfg += __shfl_down_sync(0xFFFFFFFFu, nfg, o);
        nbg += __shfl_down_sync(0xFFFFFFFFu, nbg, o);
    }
    const int wid = tid >> 5, lid = tid & 31;
    if (lid == 0) {
        wsum[wid][0] = (double)sfg;  wsum[wid][1] = (double)sbg;
        wcnt[wid][0] = nfg;          wcnt[wid][1] = nbg;
    }
    __syncthreads();
    if (tid == 0) {
        double   s0 = 0.0, s1 = 0.0;
        unsigned c0 = 0u,  c1 = 0u;
#pragma unroll
        for (int k = 0; k < 8; k++) {
            s0 += wsum[k][0];  s1 += wsum[k][1];
            c0 += wcnt[k][0];  c1 += wcnt[k][1];
        }
        g_sum[b][0] = s0;  g_sum[b][1] = s1;
        g_cnt[b][0] = c0;  g_cnt[b][1] = c1;
        __threadfence();
        isLast = (atomicAdd(&g_ctr, 1u) == NBLK - 1);
    }
    __syncthreads();

    // ---- last block: parallel deterministic final reduction + loss ----
    if (isLast) {
        if (tid < 32) {
            int ph = tid >> 3, sub = tid & 7;  // phase 0..3, 8 lanes each
            int base = (ph >> 1) * 64;         // blocks of that image
            int e    = ph & 1;
            double   s = 0.0;
            unsigned c = 0u;
#pragma unroll
            for (int t = 0; t < 8; t++) {
                int k = base + sub + 8 * t;
                s += g_sum[k][e];
                c += g_cnt[k][e];
            }
#pragma unroll
            for (int o = 4; o > 0; o >>= 1) {
                s += __shfl_down_sync(0xFFFFFFFFu, s, o);
                c += __shfl_down_sync(0xFFFFFFFFu, c, o);
            }
            if (sub == 0) { fsum[ph] = s; fcnt[ph] = c; }
        }
        __syncthreads();
        if (tid == 0) {
            const double VX2   = 21.0;         // 2 * VOXEL_SIZE
            const double TH_MU = 48.7578, TH_SD = 5.2874;
            const double SP_MU = 156.729, SP_SD = 46.1809;
            double n0 = fcnt[0] ? (double)fcnt[0] : 1.0;
            double n1 = fcnt[1] ? (double)fcnt[1] : 1.0;
            double n2 = fcnt[2] ? (double)fcnt[2] : 1.0;
            double n3 = fcnt[3] ? (double)fcnt[3] : 1.0;
            double tl = VX2 * fsum[0] / n0;    // thickness  (img)
            double sl = VX2 * fsum[1] / n1;    // separation (img)
            double th = VX2 * fsum[2] / n2;    // thickness  (tgt)
            double sh = VX2 * fsum[3] / n3;    // separation (tgt)
            double l1 = (tl - TH_MU) / TH_SD - (th - TH_MU) / TH_SD;
            double l7 = (sl - SP_MU) / SP_SD - (sh - SP_MU) / SP_SD;
            out[0] = (float)(0.5 * (l1 * l1 + l7 * l7));
            g_ctr = 0;                         // reset for next graph replay
        }
    }
}

extern "C" void kernel_launch(void* const* d_in, const int* in_sizes, int n_in,
                              void* d_out, int out_size) {
    const float* img  = (const float*)d_in[0];
    const float* mask = (const float*)d_in[1];
    const float* tgt  = (const float*)d_in[2];
    morph_all<<<NBLK, TPB>>>(img, mask, tgt, (float*)d_out);
}